// round 5
// baseline (speedup 1.0000x reference)
#include <cuda_runtime.h>
#include <cuda_bf16.h>
#include <cuda_fp16.h>
#include <math.h>

typedef unsigned long long ull;

#define N_NODES 50000
#define E_EDGES 600000
#define B_GR    128
#define D       128
#define NHEAD   4
#define DH      32
#define NEG_SLOPE 0.2f
#define SCAN_NBLK ((N_NODES + 255) / 256)   // 196
#define EB ((E_EDGES + 255) / 256)          // 2344
#define WB ((N_NODES * 32 + 255) / 256)     // 6250

// ---------------- device scratch ----------------
__device__ int    g_is64;
__device__ int    d_src[E_EDGES];
__device__ int    d_dst[E_EDGES];
__device__ int    d_gid[N_NODES];
__device__ int    d_count[N_NODES];
__device__ int    d_rowptr[N_NODES + 1];
__device__ int    d_cur[N_NODES];
__device__ int    d_col[E_EDGES];
__device__ int    d_part[SCAN_NBLK];
__device__ float  d_z[N_NODES * D];
__device__ __half d_zh[N_NODES * D];     // fp16 mirror of z for neighbor gathers
__device__ float  d_as[N_NODES * NHEAD];
__device__ float  d_ad[N_NODES * NHEAD];
__device__ float  d_hA[N_NODES * D];
__device__ float  d_hB[N_NODES * D];
__device__ float  d_z0[D];
__device__ float  d_gsum[B_GR * D];
__device__ int    d_gcnt[B_GR];

// ---------------- helpers ----------------
__device__ __forceinline__ float lrelu(float x) { return x >= 0.f ? x : NEG_SLOPE * x; }
__device__ __forceinline__ float eluf(float x)  { return x > 0.f ? x : expm1f(x); }
__device__ __forceinline__ void ffma2(ull &d, ull a, ull b) {
    asm("fma.rn.f32x2 %0, %1, %2, %0;" : "+l"(d) : "l"(a), "l"(b));
}
__device__ __forceinline__ ull dup2(float v) {
    ull r;
    asm("mov.b64 %0, {%1, %1};" : "=l"(r) : "f"(v));
    return r;
}

// ---------------- prep: zero scratch + dtype detect + z0 ----------------
__global__ void prep_k(const int* __restrict__ edge32,
                       const float* __restrict__ emb, const float* __restrict__ W0) {
    int i = blockIdx.x * 256 + threadIdx.x;
    if (i < N_NODES) { d_count[i] = 0; d_cur[i] = 0; }
    if (i < B_GR * D) d_gsum[i] = 0.f;
    if (i < B_GR)     d_gcnt[i] = 0;

    if (blockIdx.x == 0) {
        // int64 LE with values < 2^31 -> every odd 32-bit word is 0.
        __shared__ int any_nz;
        if (threadIdx.x == 0) { any_nz = 0; d_rowptr[N_NODES] = E_EDGES; }
        __syncthreads();
        int nz = 0;
        for (int t = threadIdx.x; t < 1024; t += 256)
            if (edge32[2 * t + 1] != 0) nz = 1;
        if (nz) atomicOr(&any_nz, 1);
        __syncthreads();
        if (threadIdx.x == 0) g_is64 = any_nz ? 0 : 1;
    }
    if (blockIdx.x == 1 && threadIdx.x < D) {
        int c = threadIdx.x;
        float acc = 0.f;
        for (int k = 0; k < D; k++) acc += emb[k] * W0[k * D + c];
        d_z0[c] = acc;
    }
}

// ---------------- decode edges+ptr, fused in-degree histogram ----------------
__global__ void decode_k(const void* __restrict__ edge, const void* __restrict__ ptr) {
    int b = blockIdx.x;
    if (b < EB) {
        int e = b * 256 + threadIdx.x;
        if (e >= E_EDGES) return;
        int s, d;
        if (g_is64) {
            const long long* p = (const long long*)edge;
            s = (int)p[e]; d = (int)p[E_EDGES + e];
        } else {
            const int* p = (const int*)edge;
            s = p[e]; d = p[E_EDGES + e];
        }
        d_src[e] = s; d_dst[e] = d;
        atomicAdd(&d_count[d], 1);
    } else {
        int n = (b - EB) * 256 + threadIdx.x;
        if (n >= N_NODES) return;
        d_gid[n] = g_is64 ? (int)((const long long*)ptr)[n] : ((const int*)ptr)[n];
    }
}

// ---------------- scan a: per-block sums of counts ----------------
__global__ void scan_a_k() {
    __shared__ int sh[256];
    int i = blockIdx.x * 256 + threadIdx.x;
    int v = (i < N_NODES) ? d_count[i] : 0;
    sh[threadIdx.x] = v;
    __syncthreads();
    for (int off = 128; off > 0; off >>= 1) {
        if (threadIdx.x < off) sh[threadIdx.x] += sh[threadIdx.x + off];
        __syncthreads();
    }
    if (threadIdx.x == 0) d_part[blockIdx.x] = sh[0];
}

// ---------------- scan b: every block reduces the partials itself ----------------
__global__ void scan_b_k() {
    __shared__ int sh[256];
    __shared__ int red[256];
    int b = blockIdx.x;
    int t = threadIdx.x;
    int pv = (t < SCAN_NBLK && t < b) ? d_part[t] : 0;
    red[t] = pv;
    __syncthreads();
    for (int off = 128; off > 0; off >>= 1) {
        if (t < off) red[t] += red[t + off];
        __syncthreads();
    }
    int pre = red[0];
    int i = b * 256 + t;
    int v = (i < N_NODES) ? d_count[i] : 0;
    sh[t] = v;
    __syncthreads();
    for (int off = 1; off < 256; off <<= 1) {
        int tv = (t >= off) ? sh[t - off] : 0;
        __syncthreads();
        sh[t] += tv;
        __syncthreads();
    }
    if (i < N_NODES) d_rowptr[i] = pre + sh[t] - v;  // exclusive
}

// ---------------- CSR fill + layer-1 analytic shortcut (fused) ----------------
__global__ void fill_h1_k(const float* __restrict__ emb) {
    int b = blockIdx.x;
    if (b < EB) {
        int e = b * 256 + threadIdx.x;
        if (e >= E_EDGES) return;
        int d = d_dst[e];
        int pos = atomicAdd(&d_cur[d], 1);
        d_col[d_rowptr[d] + pos] = d_src[e];
    } else {
        int i = (b - EB) * 256 + threadIdx.x;   // float4 index
        if (i >= N_NODES * 32) return;
        int n = i >> 5, q = i & 31;
        float m = (float)(d_count[n] + 2);      // 1 + deg_total
        float4 z = ((const float4*)d_z0)[q];
        float4 e4 = ((const float4*)emb)[q];
        float4 o;
        o.x = eluf(m * z.x) + e4.x;
        o.y = eluf(m * z.y) + e4.y;
        o.z = eluf(m * z.z) + e4.z;
        o.w = eluf(m * z.w) + e4.w;
        ((float4*)d_hA)[i] = o;
    }
}

// ---------------- GEMM: z = h @ W via packed fma.rn.f32x2 (+ fp16 mirror) ----------------
__global__ __launch_bounds__(256) void gemm_k(const float* __restrict__ W, int sel) {
    const float* __restrict__ hin = sel ? d_hB : d_hA;
    __shared__ float Ws[32 * 128];
    __shared__ ull   Hs2[32 * 129];
    int tid = threadIdx.x;
    int tx = tid & 15, ty = tid >> 4;
    int row0 = blockIdx.x * 128;

    ull acc[8][4];
#pragma unroll
    for (int i = 0; i < 8; i++)
#pragma unroll
        for (int j = 0; j < 4; j++) acc[i][j] = 0ull;

    for (int k0 = 0; k0 < 128; k0 += 32) {
        if (k0) __syncthreads();
#pragma unroll
        for (int i = 0; i < 4; i++) {
            int idx = tid + i * 256;           // 1024 float4
            int kk = idx >> 5, c4 = idx & 31;
            ((float4*)Ws)[kk * 32 + c4] = ((const float4*)W)[(k0 + kk) * 32 + c4];
        }
#pragma unroll
        for (int i = 0; i < 4; i++) {
            int idx = tid + i * 256;           // 1024 float4
            int r = idx >> 3, k4 = idx & 7;
            int row = row0 + r;
            float4 v = make_float4(0.f, 0.f, 0.f, 0.f);
            if (row < N_NODES) v = ((const float4*)hin)[row * 32 + (k0 >> 2) + k4];
            Hs2[(k4 * 4 + 0) * 129 + r] = dup2(v.x);
            Hs2[(k4 * 4 + 1) * 129 + r] = dup2(v.y);
            Hs2[(k4 * 4 + 2) * 129 + r] = dup2(v.z);
            Hs2[(k4 * 4 + 3) * 129 + r] = dup2(v.w);
        }
        __syncthreads();
#pragma unroll 8
        for (int kk = 0; kk < 32; kk++) {
            ull bb[4];
            const ull* wrow = (const ull*)(Ws + kk * 128);
#pragma unroll
            for (int j = 0; j < 4; j++) bb[j] = wrow[tx + 16 * j];
#pragma unroll
            for (int i = 0; i < 8; i++) {
                ull a = Hs2[kk * 129 + ty * 8 + i];
#pragma unroll
                for (int j = 0; j < 4; j++) ffma2(acc[i][j], a, bb[j]);
            }
        }
    }
#pragma unroll
    for (int i = 0; i < 8; i++) {
        int row = row0 + ty * 8 + i;
        if (row < N_NODES) {
            ull* zrow = (ull*)(d_z + row * D);
            __half2* hrow = (__half2*)(d_zh + row * D);
#pragma unroll
            for (int j = 0; j < 4; j++) {
                zrow[tx + 16 * j] = acc[i][j];
                float2 f = *(float2*)&acc[i][j];
                hrow[tx + 16 * j] = __floats2half2_rn(f.x, f.y);
            }
        }
    }
}

// ---------------- attention logits a_s, a_d ----------------
__global__ void att_k(const float* __restrict__ att_s, const float* __restrict__ att_d) {
    int warp = (blockIdx.x * blockDim.x + threadIdx.x) >> 5;
    if (warp >= N_NODES) return;
    int lane = threadIdx.x & 31;
    int head = lane >> 3;
    float4 z = ((const float4*)d_z)[warp * 32 + lane];
    float4 s = ((const float4*)att_s)[head * 8 + (lane & 7)];
    float4 t = ((const float4*)att_d)[head * 8 + (lane & 7)];
    float ps = z.x * s.x + z.y * s.y + z.z * s.z + z.w * s.w;
    float pd = z.x * t.x + z.y * t.y + z.z * t.z + z.w * t.w;
#pragma unroll
    for (int o = 4; o >= 1; o >>= 1) {
        ps += __shfl_xor_sync(0xffffffffu, ps, o);
        pd += __shfl_xor_sync(0xffffffffu, pd, o);
    }
    if ((lane & 7) == 0) {
        d_as[warp * 4 + head] = ps;
        d_ad[warp * 4 + head] = pd;
    }
}

// ---------------- fused ONLINE softmax + aggregation + elu + residual ----------------
// Warp per node, single edge pass, fp16 neighbor gather (halves L2 bytes).
__global__ void agg_k(int sel) {
    const float* __restrict__ hin = sel ? d_hB : d_hA;
    float* __restrict__ hout = sel ? d_hA : d_hB;
    int n = (blockIdx.x * blockDim.x + threadIdx.x) >> 5;
    if (n >= N_NODES) return;
    int lane = threadIdx.x & 31;
    int head = lane >> 3;

    float ad = d_ad[n * 4 + head];
    float amax = lrelu(d_as[n * 4 + head] + ad);   // self logit
    int beg = d_rowptr[n], end = d_rowptr[n + 1];

    float den = 1.f;                               // exp(self - self)
    float4 zv = ((const float4*)d_z)[n * 32 + lane];
    float4 S0 = zv;
    float4 S1 = zv;

#pragma unroll 2
    for (int e = beg; e < end; e++) {
        int s = __ldg(&d_col[e]);
        float l = lrelu(__ldg(&d_as[s * 4 + head]) + ad);
        float nm = fmaxf(amax, l);
        float c = __expf(amax - nm);
        float w = __expf(l - nm);
        amax = nm;
        uint2 u = __ldg((const uint2*)(d_zh + s * D) + lane);
        float2 f0 = __half22float2(*(__half2*)&u.x);
        float2 f1 = __half22float2(*(__half2*)&u.y);
        den = fmaf(den, c, w);
        S0.x += f0.x; S0.y += f0.y; S0.z += f1.x; S0.w += f1.y;
        S1.x = fmaf(S1.x, c, w * f0.x);
        S1.y = fmaf(S1.y, c, w * f0.y);
        S1.z = fmaf(S1.z, c, w * f1.x);
        S1.w = fmaf(S1.w, c, w * f1.y);
    }
    float inv = 1.f / den;
    float4 r = ((const float4*)hin)[n * 32 + lane];
    float4 o;
    o.x = eluf(fmaf(S1.x, inv, S0.x)) + r.x;
    o.y = eluf(fmaf(S1.y, inv, S0.y)) + r.y;
    o.z = eluf(fmaf(S1.z, inv, S0.z)) + r.z;
    o.w = eluf(fmaf(S1.w, inv, S0.w)) + r.w;
    ((float4*)hout)[n * 32 + lane] = o;
}

// ---------------- graph readout ----------------
__global__ void readout_k() {
    int warp = (blockIdx.x * blockDim.x + threadIdx.x) >> 5;
    int lane = threadIdx.x & 31;
    int n0 = warp * 64;
    if (n0 >= N_NODES) return;
    int n1 = min(n0 + 64, N_NODES);
    int gcur = d_gid[n0];
    float4 acc = make_float4(0.f, 0.f, 0.f, 0.f);
    int run = 0;
    for (int n = n0; n < n1; n++) {
        int g = d_gid[n];
        if (g != gcur) {
            atomicAdd(&d_gsum[gcur * D + lane * 4 + 0], acc.x);
            atomicAdd(&d_gsum[gcur * D + lane * 4 + 1], acc.y);
            atomicAdd(&d_gsum[gcur * D + lane * 4 + 2], acc.z);
            atomicAdd(&d_gsum[gcur * D + lane * 4 + 3], acc.w);
            if (lane == 0) atomicAdd(&d_gcnt[gcur], run);
            acc = make_float4(0.f, 0.f, 0.f, 0.f);
            run = 0; gcur = g;
        }
        float4 v = ((const float4*)d_hA)[n * 32 + lane];
        acc.x += v.x; acc.y += v.y; acc.z += v.z; acc.w += v.w;
        run++;
    }
    atomicAdd(&d_gsum[gcur * D + lane * 4 + 0], acc.x);
    atomicAdd(&d_gsum[gcur * D + lane * 4 + 1], acc.y);
    atomicAdd(&d_gsum[gcur * D + lane * 4 + 2], acc.z);
    atomicAdd(&d_gsum[gcur * D + lane * 4 + 3], acc.w);
    if (lane == 0) atomicAdd(&d_gcnt[gcur], run);
}

// ---------------- MLP readout ----------------
__global__ void mlp_k(const float* __restrict__ w0, const float* __restrict__ b0,
                      const float* __restrict__ w1, const float* __restrict__ b1,
                      float* __restrict__ y) {
    int b = blockIdx.x;
    int j = threadIdx.x;            // 64 hidden units
    float inv = 1.f / fmaxf((float)d_gcnt[b], 1.f);
    float acc = b0[j];
    for (int k = 0; k < D; k++) {
        float g = fmaxf(d_gsum[b * D + k] * inv, 0.f);
        acc = fmaf(g, w0[k * 64 + j], acc);
    }
    float t = fmaxf(acc, 0.f) * w1[j];
    __shared__ float sh[64];
    sh[j] = t;
    __syncthreads();
    for (int off = 32; off > 0; off >>= 1) {
        if (j < off) sh[j] += sh[j + off];
        __syncthreads();
    }
    if (j == 0) y[b] = sh[0] + b1[0];
}

// ---------------- launcher ----------------
extern "C" void kernel_launch(void* const* d_in, const int* in_sizes, int n_in,
                              void* d_out, int out_size) {
    const void*  edge  = d_in[1];
    const void*  ptr   = d_in[2];
    const float* emb   = (const float*)d_in[3];
    const float* lin_w = (const float*)d_in[4];
    const float* att_s = (const float*)d_in[5];
    const float* att_d = (const float*)d_in[6];
    const float* w0    = (const float*)d_in[7];
    const float* b0    = (const float*)d_in[8];
    const float* w1    = (const float*)d_in[9];
    const float* b1    = (const float*)d_in[10];
    float* y = (float*)d_out;

    const int NB = SCAN_NBLK;

    prep_k<<<NB, 256>>>((const int*)edge, emb, lin_w);
    decode_k<<<EB + NB, 256>>>(edge, ptr);
    scan_a_k<<<NB, 256>>>();
    scan_b_k<<<NB, 256>>>();
    fill_h1_k<<<EB + WB, 256>>>(emb);

    for (int l = 1; l < 3; l++) {
        int sel = l - 1;   // 0: hA->hB, 1: hB->hA
        gemm_k<<<(N_NODES + 127) / 128, 256>>>(lin_w + l * D * D, sel);
        att_k<<<WB, 256>>>(att_s + l * NHEAD * DH, att_d + l * NHEAD * DH);
        agg_k<<<WB, 256>>>(sel);
    }

    readout_k<<<((N_NODES + 63) / 64 * 32 + 255) / 256, 256>>>();
    mlp_k<<<B_GR, 64>>>(w0, b0, w1, b1, y);
}

// round 6
// speedup vs baseline: 1.0023x; 1.0023x over previous
#include <cuda_runtime.h>
#include <cuda_bf16.h>
#include <math.h>

typedef unsigned long long ull;

#define N_NODES 50000
#define E_EDGES 600000
#define B_GR    128
#define D       128
#define NHEAD   4
#define DH      32
#define NEG_SLOPE 0.2f
#define SCAN_NBLK ((N_NODES + 255) / 256)   // 196
#define EB ((E_EDGES + 255) / 256)          // 2344
#define WB ((N_NODES * 32 + 255) / 256)     // 6250

// ---------------- device scratch ----------------
__device__ int   g_is64;
__device__ int   d_src[E_EDGES];
__device__ int   d_dst[E_EDGES];
__device__ int   d_gid[N_NODES];
__device__ int   d_count[N_NODES];
__device__ int   d_rowptr[N_NODES + 1];
__device__ int   d_cur[N_NODES];
__device__ int   d_col[E_EDGES];
__device__ int   d_part[SCAN_NBLK];
__device__ float d_z[N_NODES * D];
__device__ float d_as[N_NODES * NHEAD];
__device__ float d_ad[N_NODES * NHEAD];
__device__ float d_hA[N_NODES * D];
__device__ float d_hB[N_NODES * D];
__device__ float d_z0[D];
__device__ float d_gsum[B_GR * D];
__device__ int   d_gcnt[B_GR];

// ---------------- helpers ----------------
__device__ __forceinline__ float lrelu(float x) { return x >= 0.f ? x : NEG_SLOPE * x; }
__device__ __forceinline__ float eluf(float x)  { return x > 0.f ? x : expm1f(x); }
__device__ __forceinline__ void ffma2(ull &d, ull a, ull b) {
    asm("fma.rn.f32x2 %0, %1, %2, %0;" : "+l"(d) : "l"(a), "l"(b));
}
__device__ __forceinline__ ull dup2(float v) {
    ull r;
    asm("mov.b64 %0, {%1, %1};" : "=l"(r) : "f"(v));
    return r;
}

// ---------------- prep: zero scratch + dtype detect + z0 ----------------
__global__ void prep_k(const int* __restrict__ edge32,
                       const float* __restrict__ emb, const float* __restrict__ W0) {
    int i = blockIdx.x * 256 + threadIdx.x;
    if (i < N_NODES) { d_count[i] = 0; d_cur[i] = 0; }
    if (i < B_GR * D) d_gsum[i] = 0.f;
    if (i < B_GR)     d_gcnt[i] = 0;

    if (blockIdx.x == 0) {
        // int64 LE with values < 2^31 -> every odd 32-bit word is 0.
        __shared__ int any_nz;
        if (threadIdx.x == 0) { any_nz = 0; d_rowptr[N_NODES] = E_EDGES; }
        __syncthreads();
        int nz = 0;
        for (int t = threadIdx.x; t < 1024; t += 256)
            if (edge32[2 * t + 1] != 0) nz = 1;
        if (nz) atomicOr(&any_nz, 1);
        __syncthreads();
        if (threadIdx.x == 0) g_is64 = any_nz ? 0 : 1;
    }
    if (blockIdx.x == 1 && threadIdx.x < D) {
        int c = threadIdx.x;
        float acc = 0.f;
        for (int k = 0; k < D; k++) acc += emb[k] * W0[k * D + c];
        d_z0[c] = acc;
    }
}

// ---------------- decode edges+ptr, fused in-degree histogram ----------------
__global__ void decode_k(const void* __restrict__ edge, const void* __restrict__ ptr) {
    int b = blockIdx.x;
    if (b < EB) {
        int e = b * 256 + threadIdx.x;
        if (e >= E_EDGES) return;
        int s, d;
        if (g_is64) {
            const long long* p = (const long long*)edge;
            s = (int)p[e]; d = (int)p[E_EDGES + e];
        } else {
            const int* p = (const int*)edge;
            s = p[e]; d = p[E_EDGES + e];
        }
        d_src[e] = s; d_dst[e] = d;
        atomicAdd(&d_count[d], 1);
    } else {
        int n = (b - EB) * 256 + threadIdx.x;
        if (n >= N_NODES) return;
        d_gid[n] = g_is64 ? (int)((const long long*)ptr)[n] : ((const int*)ptr)[n];
    }
}

// ---------------- scan a: per-block sums of counts ----------------
__global__ void scan_a_k() {
    __shared__ int sh[256];
    int i = blockIdx.x * 256 + threadIdx.x;
    int v = (i < N_NODES) ? d_count[i] : 0;
    sh[threadIdx.x] = v;
    __syncthreads();
    for (int off = 128; off > 0; off >>= 1) {
        if (threadIdx.x < off) sh[threadIdx.x] += sh[threadIdx.x + off];
        __syncthreads();
    }
    if (threadIdx.x == 0) d_part[blockIdx.x] = sh[0];
}

// ---------------- scan b: every block reduces the partials itself ----------------
__global__ void scan_b_k() {
    __shared__ int sh[256];
    __shared__ int red[256];
    int b = blockIdx.x;
    int t = threadIdx.x;
    int pv = (t < SCAN_NBLK && t < b) ? d_part[t] : 0;
    red[t] = pv;
    __syncthreads();
    for (int off = 128; off > 0; off >>= 1) {
        if (t < off) red[t] += red[t + off];
        __syncthreads();
    }
    int pre = red[0];
    int i = b * 256 + t;
    int v = (i < N_NODES) ? d_count[i] : 0;
    sh[t] = v;
    __syncthreads();
    for (int off = 1; off < 256; off <<= 1) {
        int tv = (t >= off) ? sh[t - off] : 0;
        __syncthreads();
        sh[t] += tv;
        __syncthreads();
    }
    if (i < N_NODES) d_rowptr[i] = pre + sh[t] - v;  // exclusive
}

// ---------------- CSR fill + layer-1 analytic shortcut (fused) ----------------
__global__ void fill_h1_k(const float* __restrict__ emb) {
    int b = blockIdx.x;
    if (b < EB) {
        int e = b * 256 + threadIdx.x;
        if (e >= E_EDGES) return;
        int d = d_dst[e];
        int pos = atomicAdd(&d_cur[d], 1);
        d_col[d_rowptr[d] + pos] = d_src[e];
    } else {
        int i = (b - EB) * 256 + threadIdx.x;   // float4 index
        if (i >= N_NODES * 32) return;
        int n = i >> 5, q = i & 31;
        float m = (float)(d_count[n] + 2);      // 1 + deg_total
        float4 z = ((const float4*)d_z0)[q];
        float4 e4 = ((const float4*)emb)[q];
        float4 o;
        o.x = eluf(m * z.x) + e4.x;
        o.y = eluf(m * z.y) + e4.y;
        o.z = eluf(m * z.z) + e4.z;
        o.w = eluf(m * z.w) + e4.w;
        ((float4*)d_hA)[i] = o;
    }
}

// ---------------- GEMM: z = h @ W via packed fma.rn.f32x2 ----------------
__global__ __launch_bounds__(256) void gemm_k(const float* __restrict__ W, int sel) {
    const float* __restrict__ hin = sel ? d_hB : d_hA;
    __shared__ float Ws[32 * 128];
    __shared__ ull   Hs2[32 * 129];
    int tid = threadIdx.x;
    int tx = tid & 15, ty = tid >> 4;
    int row0 = blockIdx.x * 128;

    ull acc[8][4];
#pragma unroll
    for (int i = 0; i < 8; i++)
#pragma unroll
        for (int j = 0; j < 4; j++) acc[i][j] = 0ull;

    for (int k0 = 0; k0 < 128; k0 += 32) {
        if (k0) __syncthreads();
#pragma unroll
        for (int i = 0; i < 4; i++) {
            int idx = tid + i * 256;           // 1024 float4
            int kk = idx >> 5, c4 = idx & 31;
            ((float4*)Ws)[kk * 32 + c4] = ((const float4*)W)[(k0 + kk) * 32 + c4];
        }
#pragma unroll
        for (int i = 0; i < 4; i++) {
            int idx = tid + i * 256;           // 1024 float4
            int r = idx >> 3, k4 = idx & 7;
            int row = row0 + r;
            float4 v = make_float4(0.f, 0.f, 0.f, 0.f);
            if (row < N_NODES) v = ((const float4*)hin)[row * 32 + (k0 >> 2) + k4];
            Hs2[(k4 * 4 + 0) * 129 + r] = dup2(v.x);
            Hs2[(k4 * 4 + 1) * 129 + r] = dup2(v.y);
            Hs2[(k4 * 4 + 2) * 129 + r] = dup2(v.z);
            Hs2[(k4 * 4 + 3) * 129 + r] = dup2(v.w);
        }
        __syncthreads();
#pragma unroll 8
        for (int kk = 0; kk < 32; kk++) {
            ull bb[4];
            const ull* wrow = (const ull*)(Ws + kk * 128);
#pragma unroll
            for (int j = 0; j < 4; j++) bb[j] = wrow[tx + 16 * j];
#pragma unroll
            for (int i = 0; i < 8; i++) {
                ull a = Hs2[kk * 129 + ty * 8 + i];
#pragma unroll
                for (int j = 0; j < 4; j++) ffma2(acc[i][j], a, bb[j]);
            }
        }
    }
#pragma unroll
    for (int i = 0; i < 8; i++) {
        int row = row0 + ty * 8 + i;
        if (row < N_NODES) {
            ull* zrow = (ull*)(d_z + row * D);
#pragma unroll
            for (int j = 0; j < 4; j++) zrow[tx + 16 * j] = acc[i][j];
        }
    }
}

// ---------------- attention logits a_s, a_d ----------------
__global__ void att_k(const float* __restrict__ att_s, const float* __restrict__ att_d) {
    int warp = (blockIdx.x * blockDim.x + threadIdx.x) >> 5;
    if (warp >= N_NODES) return;
    int lane = threadIdx.x & 31;
    int head = lane >> 3;
    float4 z = ((const float4*)d_z)[warp * 32 + lane];
    float4 s = ((const float4*)att_s)[head * 8 + (lane & 7)];
    float4 t = ((const float4*)att_d)[head * 8 + (lane & 7)];
    float ps = z.x * s.x + z.y * s.y + z.z * s.z + z.w * s.w;
    float pd = z.x * t.x + z.y * t.y + z.z * t.z + z.w * t.w;
#pragma unroll
    for (int o = 4; o >= 1; o >>= 1) {
        ps += __shfl_xor_sync(0xffffffffu, ps, o);
        pd += __shfl_xor_sync(0xffffffffu, pd, o);
    }
    if ((lane & 7) == 0) {
        d_as[warp * 4 + head] = ps;
        d_ad[warp * 4 + head] = pd;
    }
}

// ---------------- fused ONLINE softmax + aggregation, 2 independent chains ----------------
// Warp per node, single edge pass. Even edges -> chain A (seeded with self),
// odd edges -> chain B. Exact flash-merge at the end. Doubles ILP on the
// serial softmax recurrence.
__global__ void agg_k(int sel) {
    const float* __restrict__ hin = sel ? d_hB : d_hA;
    float* __restrict__ hout = sel ? d_hA : d_hB;
    int n = (blockIdx.x * blockDim.x + threadIdx.x) >> 5;
    if (n >= N_NODES) return;
    int lane = threadIdx.x & 31;
    int head = lane >> 3;

    float ad = d_ad[n * 4 + head];
    int beg = d_rowptr[n], end = d_rowptr[n + 1];

    float4 zv = ((const float4*)d_z)[n * 32 + lane];
    float4 S0A = zv;
    float4 S0B = make_float4(0.f, 0.f, 0.f, 0.f);

    // chain A seeded with self edge
    float amaxA = lrelu(d_as[n * 4 + head] + ad);
    float denA = 1.f;
    float4 S1A = zv;
    // chain B empty
    float amaxB = -1e30f;
    float denB = 0.f;
    float4 S1B = make_float4(0.f, 0.f, 0.f, 0.f);

    int e = beg;
    for (; e + 1 < end; e += 2) {
        int sA = __ldg(&d_col[e]);
        int sB = __ldg(&d_col[e + 1]);
        float lA = lrelu(__ldg(&d_as[sA * 4 + head]) + ad);
        float lB = lrelu(__ldg(&d_as[sB * 4 + head]) + ad);
        float4 zA = ((const float4*)d_z)[sA * 32 + lane];
        float4 zB = ((const float4*)d_z)[sB * 32 + lane];

        float nmA = fmaxf(amaxA, lA);
        float cA = __expf(amaxA - nmA);
        float wA = __expf(lA - nmA);
        amaxA = nmA;
        denA = fmaf(denA, cA, wA);
        S0A.x += zA.x; S0A.y += zA.y; S0A.z += zA.z; S0A.w += zA.w;
        S1A.x = fmaf(S1A.x, cA, wA * zA.x);
        S1A.y = fmaf(S1A.y, cA, wA * zA.y);
        S1A.z = fmaf(S1A.z, cA, wA * zA.z);
        S1A.w = fmaf(S1A.w, cA, wA * zA.w);

        float nmB = fmaxf(amaxB, lB);
        float cB = __expf(amaxB - nmB);
        float wB = __expf(lB - nmB);
        amaxB = nmB;
        denB = fmaf(denB, cB, wB);
        S0B.x += zB.x; S0B.y += zB.y; S0B.z += zB.z; S0B.w += zB.w;
        S1B.x = fmaf(S1B.x, cB, wB * zB.x);
        S1B.y = fmaf(S1B.y, cB, wB * zB.y);
        S1B.z = fmaf(S1B.z, cB, wB * zB.z);
        S1B.w = fmaf(S1B.w, cB, wB * zB.w);
    }
    if (e < end) {                         // tail edge -> chain A
        int s = __ldg(&d_col[e]);
        float l = lrelu(__ldg(&d_as[s * 4 + head]) + ad);
        float4 z2 = ((const float4*)d_z)[s * 32 + lane];
        float nm = fmaxf(amaxA, l);
        float c = __expf(amaxA - nm);
        float w = __expf(l - nm);
        amaxA = nm;
        denA = fmaf(denA, c, w);
        S0A.x += z2.x; S0A.y += z2.y; S0A.z += z2.z; S0A.w += z2.w;
        S1A.x = fmaf(S1A.x, c, w * z2.x);
        S1A.y = fmaf(S1A.y, c, w * z2.y);
        S1A.z = fmaf(S1A.z, c, w * z2.z);
        S1A.w = fmaf(S1A.w, c, w * z2.w);
    }

    // exact merge of the two chains
    float m = fmaxf(amaxA, amaxB);
    float cA = __expf(amaxA - m);
    float cB = __expf(amaxB - m);
    float den = denA * cA + denB * cB;
    float4 S1;
    S1.x = S1A.x * cA + S1B.x * cB;
    S1.y = S1A.y * cA + S1B.y * cB;
    S1.z = S1A.z * cA + S1B.z * cB;
    S1.w = S1A.w * cA + S1B.w * cB;
    float4 S0;
    S0.x = S0A.x + S0B.x; S0.y = S0A.y + S0B.y;
    S0.z = S0A.z + S0B.z; S0.w = S0A.w + S0B.w;

    float inv = 1.f / den;
    float4 r = ((const float4*)hin)[n * 32 + lane];
    float4 o;
    o.x = eluf(fmaf(S1.x, inv, S0.x)) + r.x;
    o.y = eluf(fmaf(S1.y, inv, S0.y)) + r.y;
    o.z = eluf(fmaf(S1.z, inv, S0.z)) + r.z;
    o.w = eluf(fmaf(S1.w, inv, S0.w)) + r.w;
    ((float4*)hout)[n * 32 + lane] = o;
}

// ---------------- graph readout ----------------
__global__ void readout_k() {
    int warp = (blockIdx.x * blockDim.x + threadIdx.x) >> 5;
    int lane = threadIdx.x & 31;
    int n0 = warp * 64;
    if (n0 >= N_NODES) return;
    int n1 = min(n0 + 64, N_NODES);
    int gcur = d_gid[n0];
    float4 acc = make_float4(0.f, 0.f, 0.f, 0.f);
    int run = 0;
    for (int n = n0; n < n1; n++) {
        int g = d_gid[n];
        if (g != gcur) {
            atomicAdd(&d_gsum[gcur * D + lane * 4 + 0], acc.x);
            atomicAdd(&d_gsum[gcur * D + lane * 4 + 1], acc.y);
            atomicAdd(&d_gsum[gcur * D + lane * 4 + 2], acc.z);
            atomicAdd(&d_gsum[gcur * D + lane * 4 + 3], acc.w);
            if (lane == 0) atomicAdd(&d_gcnt[gcur], run);
            acc = make_float4(0.f, 0.f, 0.f, 0.f);
            run = 0; gcur = g;
        }
        float4 v = ((const float4*)d_hA)[n * 32 + lane];
        acc.x += v.x; acc.y += v.y; acc.z += v.z; acc.w += v.w;
        run++;
    }
    atomicAdd(&d_gsum[gcur * D + lane * 4 + 0], acc.x);
    atomicAdd(&d_gsum[gcur * D + lane * 4 + 1], acc.y);
    atomicAdd(&d_gsum[gcur * D + lane * 4 + 2], acc.z);
    atomicAdd(&d_gsum[gcur * D + lane * 4 + 3], acc.w);
    if (lane == 0) atomicAdd(&d_gcnt[gcur], run);
}

// ---------------- MLP readout ----------------
__global__ void mlp_k(const float* __restrict__ w0, const float* __restrict__ b0,
                      const float* __restrict__ w1, const float* __restrict__ b1,
                      float* __restrict__ y) {
    int b = blockIdx.x;
    int j = threadIdx.x;            // 64 hidden units
    float inv = 1.f / fmaxf((float)d_gcnt[b], 1.f);
    float acc = b0[j];
    for (int k = 0; k < D; k++) {
        float g = fmaxf(d_gsum[b * D + k] * inv, 0.f);
        acc = fmaf(g, w0[k * 64 + j], acc);
    }
    float t = fmaxf(acc, 0.f) * w1[j];
    __shared__ float sh[64];
    sh[j] = t;
    __syncthreads();
    for (int off = 32; off > 0; off >>= 1) {
        if (j < off) sh[j] += sh[j + off];
        __syncthreads();
    }
    if (j == 0) y[b] = sh[0] + b1[0];
}

// ---------------- launcher ----------------
extern "C" void kernel_launch(void* const* d_in, const int* in_sizes, int n_in,
                              void* d_out, int out_size) {
    const void*  edge  = d_in[1];
    const void*  ptr   = d_in[2];
    const float* emb   = (const float*)d_in[3];
    const float* lin_w = (const float*)d_in[4];
    const float* att_s = (const float*)d_in[5];
    const float* att_d = (const float*)d_in[6];
    const float* w0    = (const float*)d_in[7];
    const float* b0    = (const float*)d_in[8];
    const float* w1    = (const float*)d_in[9];
    const float* b1    = (const float*)d_in[10];
    float* y = (float*)d_out;

    const int NB = SCAN_NBLK;

    prep_k<<<NB, 256>>>((const int*)edge, emb, lin_w);
    decode_k<<<EB + NB, 256>>>(edge, ptr);
    scan_a_k<<<NB, 256>>>();
    scan_b_k<<<NB, 256>>>();
    fill_h1_k<<<EB + WB, 256>>>(emb);

    for (int l = 1; l < 3; l++) {
        int sel = l - 1;   // 0: hA->hB, 1: hB->hA
        gemm_k<<<(N_NODES + 127) / 128, 256>>>(lin_w + l * D * D, sel);
        att_k<<<WB, 256>>>(att_s + l * NHEAD * DH, att_d + l * NHEAD * DH);
        agg_k<<<WB, 256>>>(sel);
    }

    readout_k<<<((N_NODES + 63) / 64 * 32 + 255) / 256, 256>>>();
    mlp_k<<<B_GR, 64>>>(w0, b0, w1, b1, y);
}

// round 8
// speedup vs baseline: 1.0473x; 1.0449x over previous
#include <cuda_runtime.h>
#include <cuda_bf16.h>
#include <math.h>

typedef unsigned long long ull;

#define N_NODES 50000
#define E_EDGES 600000
#define B_GR    128
#define D       128
#define NHEAD   4
#define DH      32
#define NEG_SLOPE 0.2f
#define SCAN_NBLK ((N_NODES + 255) / 256)   // 196
#define EB ((E_EDGES + 255) / 256)          // 2344
#define WB ((N_NODES * 32 + 255) / 256)     // 6250

// ---------------- device scratch (zero-initialized at module load) ----------------
__device__ int   d_src[E_EDGES];
__device__ int   d_dst[E_EDGES];
__device__ int   d_gid[N_NODES];
__device__ int   d_count[N_NODES];          // self-cleaning: decode +1, fill -1
__device__ int   d_rowptr[N_NODES + 1];
__device__ int   d_col[E_EDGES];
__device__ float d_z[N_NODES * D];
__device__ float d_as[N_NODES * NHEAD];
__device__ float d_ad[N_NODES * NHEAD];
__device__ float d_hA[N_NODES * D];
__device__ float d_hB[N_NODES * D];
__device__ float d_z0[D];
__device__ float d_gsum[B_GR * D];
__device__ int   d_gcnt[B_GR];

// ---------------- helpers ----------------
__device__ __forceinline__ float lrelu(float x) { return x >= 0.f ? x : NEG_SLOPE * x; }
__device__ __forceinline__ float eluf(float x)  { return x > 0.f ? x : expm1f(x); }
__device__ __forceinline__ void ffma2(ull &d, ull a, ull b) {
    asm("fma.rn.f32x2 %0, %1, %2, %0;" : "+l"(d) : "l"(a), "l"(b));
}
__device__ __forceinline__ ull dup2(float v) {
    ull r;
    asm("mov.b64 %0, {%1, %1};" : "=l"(r) : "f"(v));
    return r;
}

// int64 LE with values < 2^31 -> every odd 32-bit word is 0. Checking 8 fixed
// words: for int32 data these are random node ids, P(all 8 == 0) ~ (2e-5)^8.
__device__ __forceinline__ int detect_is64(const int* __restrict__ edge32) {
    int is64 = 1;
#pragma unroll
    for (int q = 0; q < 8; q++) is64 &= (edge32[2 * q + 1] == 0);
    return is64;
}

// ---------------- decode edges+ptr + histogram + z0 + gsum zero (one kernel) ----------------
__global__ void decode_k(const void* __restrict__ edge, const void* __restrict__ ptr,
                         const float* __restrict__ emb, const float* __restrict__ W0) {
    int b = blockIdx.x;
    int t = threadIdx.x;
    __shared__ int s_is64;
    if (t == 0) s_is64 = detect_is64((const int*)edge);
    __syncthreads();
    int is64 = s_is64;

    if (b < EB) {
        int e = b * 256 + t;
        if (e >= E_EDGES) return;
        int s, d;
        if (is64) {
            const long long* p = (const long long*)edge;
            s = (int)p[e]; d = (int)p[E_EDGES + e];
        } else {
            const int* p = (const int*)edge;
            s = p[e]; d = p[E_EDGES + e];
        }
        d_src[e] = s; d_dst[e] = d;
        atomicAdd(&d_count[d], 1);
    } else if (b < EB + SCAN_NBLK) {
        int n = (b - EB) * 256 + t;
        if (n >= N_NODES) return;
        d_gid[n] = is64 ? (int)((const long long*)ptr)[n] : ((const int*)ptr)[n];
    } else if (b < EB + SCAN_NBLK + 64) {
        int i = (b - EB - SCAN_NBLK) * 256 + t;
        if (i < B_GR * D) d_gsum[i] = 0.f;
        if (i < B_GR)     d_gcnt[i] = 0;
    } else {
        if (t < D) {
            float acc = 0.f;
            for (int k = 0; k < D; k++) acc += emb[k] * W0[k * D + t];
            d_z0[t] = acc;
        }
    }
}

// ---------------- single-kernel exclusive scan (redundant block prefixes) ----------------
__global__ void scan_k() {
    __shared__ int red[256];
    __shared__ int sh[256];
    int b = blockIdx.x;
    int t = threadIdx.x;
    if (b == 0 && t == 0) d_rowptr[N_NODES] = E_EDGES;

    // prefix = sum of counts[0 .. b*256)
    int limit = b * 256;
    int psum = 0;
    for (int i = t; i < limit; i += 256) psum += d_count[i];
    red[t] = psum;
    __syncthreads();
    for (int off = 128; off > 0; off >>= 1) {
        if (t < off) red[t] += red[t + off];
        __syncthreads();
    }
    int pre = red[0];

    // local inclusive scan of this block's 256 counts
    int i = limit + t;
    int v = (i < N_NODES) ? d_count[i] : 0;
    sh[t] = v;
    __syncthreads();
    for (int off = 1; off < 256; off <<= 1) {
        int tv = (t >= off) ? sh[t - off] : 0;
        __syncthreads();
        sh[t] += tv;
        __syncthreads();
    }
    if (i < N_NODES) d_rowptr[i] = pre + sh[t] - v;  // exclusive
}

// ---------------- CSR fill (self-cleaning counters) + layer-1 shortcut ----------------
__global__ void fill_h1_k(const float* __restrict__ emb) {
    int b = blockIdx.x;
    if (b < EB) {
        int e = b * 256 + threadIdx.x;
        if (e >= E_EDGES) return;
        int d = d_dst[e];
        int old = atomicSub(&d_count[d], 1);     // counters return to 0 for next run
        d_col[d_rowptr[d] + old - 1] = d_src[e];
    } else {
        int i = (b - EB) * 256 + threadIdx.x;    // float4 index
        if (i >= N_NODES * 32) return;
        int n = i >> 5, q = i & 31;
        int deg = d_rowptr[n + 1] - d_rowptr[n]; // race-free (count is being decremented)
        float m = (float)(deg + 2);              // 1 + deg_total, deg_total = deg + 1
        float4 z = ((const float4*)d_z0)[q];
        float4 e4 = ((const float4*)emb)[q];
        float4 o;
        o.x = eluf(m * z.x) + e4.x;
        o.y = eluf(m * z.y) + e4.y;
        o.z = eluf(m * z.z) + e4.z;
        o.w = eluf(m * z.w) + e4.w;
        ((float4*)d_hA)[i] = o;
    }
}

// ---------------- GEMM: z = h @ W via packed fma.rn.f32x2 ----------------
__global__ __launch_bounds__(256) void gemm_k(const float* __restrict__ W, int sel) {
    const float* __restrict__ hin = sel ? d_hB : d_hA;
    __shared__ float Ws[32 * 128];
    __shared__ ull   Hs2[32 * 129];
    int tid = threadIdx.x;
    int tx = tid & 15, ty = tid >> 4;
    int row0 = blockIdx.x * 128;

    ull acc[8][4];
#pragma unroll
    for (int i = 0; i < 8; i++)
#pragma unroll
        for (int j = 0; j < 4; j++) acc[i][j] = 0ull;

    for (int k0 = 0; k0 < 128; k0 += 32) {
        if (k0) __syncthreads();
#pragma unroll
        for (int i = 0; i < 4; i++) {
            int idx = tid + i * 256;           // 1024 float4
            int kk = idx >> 5, c4 = idx & 31;
            ((float4*)Ws)[kk * 32 + c4] = ((const float4*)W)[(k0 + kk) * 32 + c4];
        }
#pragma unroll
        for (int i = 0; i < 4; i++) {
            int idx = tid + i * 256;           // 1024 float4
            int r = idx >> 3, k4 = idx & 7;
            int row = row0 + r;
            float4 v = make_float4(0.f, 0.f, 0.f, 0.f);
            if (row < N_NODES) v = ((const float4*)hin)[row * 32 + (k0 >> 2) + k4];
            Hs2[(k4 * 4 + 0) * 129 + r] = dup2(v.x);
            Hs2[(k4 * 4 + 1) * 129 + r] = dup2(v.y);
            Hs2[(k4 * 4 + 2) * 129 + r] = dup2(v.z);
            Hs2[(k4 * 4 + 3) * 129 + r] = dup2(v.w);
        }
        __syncthreads();
#pragma unroll 8
        for (int kk = 0; kk < 32; kk++) {
            ull bb[4];
            const ull* wrow = (const ull*)(Ws + kk * 128);
#pragma unroll
            for (int j = 0; j < 4; j++) bb[j] = wrow[tx + 16 * j];
#pragma unroll
            for (int i = 0; i < 8; i++) {
                ull a = Hs2[kk * 129 + ty * 8 + i];
#pragma unroll
                for (int j = 0; j < 4; j++) ffma2(acc[i][j], a, bb[j]);
            }
        }
    }
#pragma unroll
    for (int i = 0; i < 8; i++) {
        int row = row0 + ty * 8 + i;
        if (row < N_NODES) {
            ull* zrow = (ull*)(d_z + row * D);
#pragma unroll
            for (int j = 0; j < 4; j++) zrow[tx + 16 * j] = acc[i][j];
        }
    }
}

// ---------------- attention logits a_s, a_d ----------------
__global__ void att_k(const float* __restrict__ att_s, const float* __restrict__ att_d) {
    int warp = (blockIdx.x * blockDim.x + threadIdx.x) >> 5;
    if (warp >= N_NODES) return;
    int lane = threadIdx.x & 31;
    int head = lane >> 3;
    float4 z = ((const float4*)d_z)[warp * 32 + lane];
    float4 s = ((const float4*)att_s)[head * 8 + (lane & 7)];
    float4 t = ((const float4*)att_d)[head * 8 + (lane & 7)];
    float ps = z.x * s.x + z.y * s.y + z.z * s.z + z.w * s.w;
    float pd = z.x * t.x + z.y * t.y + z.z * t.z + z.w * t.w;
#pragma unroll
    for (int o = 4; o >= 1; o >>= 1) {
        ps += __shfl_xor_sync(0xffffffffu, ps, o);
        pd += __shfl_xor_sync(0xffffffffu, pd, o);
    }
    if ((lane & 7) == 0) {
        d_as[warp * 4 + head] = ps;
        d_ad[warp * 4 + head] = pd;
    }
}

// ---------------- fused ONLINE softmax + aggregation + elu + residual ----------------
// (R4 version — best known; do not fatten this loop.)
__global__ void agg_k(int sel) {
    const float* __restrict__ hin = sel ? d_hB : d_hA;
    float* __restrict__ hout = sel ? d_hA : d_hB;
    int n = (blockIdx.x * blockDim.x + threadIdx.x) >> 5;
    if (n >= N_NODES) return;
    int lane = threadIdx.x & 31;
    int head = lane >> 3;

    float ad = d_ad[n * 4 + head];
    float amax = lrelu(d_as[n * 4 + head] + ad);   // self logit
    int beg = d_rowptr[n], end = d_rowptr[n + 1];

    float den = 1.f;                               // exp(self - self)
    float4 zv = ((const float4*)d_z)[n * 32 + lane];
    float4 S0 = zv;
    float4 S1 = zv;

#pragma unroll 2
    for (int e = beg; e < end; e++) {
        int s = __ldg(&d_col[e]);
        float l = lrelu(__ldg(&d_as[s * 4 + head]) + ad);
        float nm = fmaxf(amax, l);
        float c = __expf(amax - nm);
        float w = __expf(l - nm);
        amax = nm;
        float4 z2 = ((const float4*)d_z)[s * 32 + lane];
        den = fmaf(den, c, w);
        S0.x += z2.x; S0.y += z2.y; S0.z += z2.z; S0.w += z2.w;
        S1.x = fmaf(S1.x, c, w * z2.x);
        S1.y = fmaf(S1.y, c, w * z2.y);
        S1.z = fmaf(S1.z, c, w * z2.z);
        S1.w = fmaf(S1.w, c, w * z2.w);
    }
    float inv = 1.f / den;
    float4 r = ((const float4*)hin)[n * 32 + lane];
    float4 o;
    o.x = eluf(fmaf(S1.x, inv, S0.x)) + r.x;
    o.y = eluf(fmaf(S1.y, inv, S0.y)) + r.y;
    o.z = eluf(fmaf(S1.z, inv, S0.z)) + r.z;
    o.w = eluf(fmaf(S1.w, inv, S0.w)) + r.w;
    ((float4*)hout)[n * 32 + lane] = o;
}

// ---------------- graph readout ----------------
__global__ void readout_k() {
    int warp = (blockIdx.x * blockDim.x + threadIdx.x) >> 5;
    int lane = threadIdx.x & 31;
    int n0 = warp * 64;
    if (n0 >= N_NODES) return;
    int n1 = min(n0 + 64, N_NODES);
    int gcur = d_gid[n0];
    float4 acc = make_float4(0.f, 0.f, 0.f, 0.f);
    int run = 0;
    for (int n = n0; n < n1; n++) {
        int g = d_gid[n];
        if (g != gcur) {
            atomicAdd(&d_gsum[gcur * D + lane * 4 + 0], acc.x);
            atomicAdd(&d_gsum[gcur * D + lane * 4 + 1], acc.y);
            atomicAdd(&d_gsum[gcur * D + lane * 4 + 2], acc.z);
            atomicAdd(&d_gsum[gcur * D + lane * 4 + 3], acc.w);
            if (lane == 0) atomicAdd(&d_gcnt[gcur], run);
            acc = make_float4(0.f, 0.f, 0.f, 0.f);
            run = 0; gcur = g;
        }
        float4 v = ((const float4*)d_hA)[n * 32 + lane];
        acc.x += v.x; acc.y += v.y; acc.z += v.z; acc.w += v.w;
        run++;
    }
    atomicAdd(&d_gsum[gcur * D + lane * 4 + 0], acc.x);
    atomicAdd(&d_gsum[gcur * D + lane * 4 + 1], acc.y);
    atomicAdd(&d_gsum[gcur * D + lane * 4 + 2], acc.z);
    atomicAdd(&d_gsum[gcur * D + lane * 4 + 3], acc.w);
    if (lane == 0) atomicAdd(&d_gcnt[gcur], run);
}

// ---------------- MLP readout ----------------
__global__ void mlp_k(const float* __restrict__ w0, const float* __restrict__ b0,
                      const float* __restrict__ w1, const float* __restrict__ b1,
                      float* __restrict__ y) {
    int b = blockIdx.x;
    int j = threadIdx.x;            // 64 hidden units
    float inv = 1.f / fmaxf((float)d_gcnt[b], 1.f);
    float acc = b0[j];
    for (int k = 0; k < D; k++) {
        float g = fmaxf(d_gsum[b * D + k] * inv, 0.f);
        acc = fmaf(g, w0[k * 64 + j], acc);
    }
    float t = fmaxf(acc, 0.f) * w1[j];
    __shared__ float sh[64];
    sh[j] = t;
    __syncthreads();
    for (int off = 32; off > 0; off >>= 1) {
        if (j < off) sh[j] += sh[j + off];
        __syncthreads();
    }
    if (j == 0) y[b] = sh[0] + b1[0];
}

// ---------------- launcher ----------------
extern "C" void kernel_launch(void* const* d_in, const int* in_sizes, int n_in,
                              void* d_out, int out_size) {
    const void*  edge  = d_in[1];
    const void*  ptr   = d_in[2];
    const float* emb   = (const float*)d_in[3];
    const float* lin_w = (const float*)d_in[4];
    const float* att_s = (const float*)d_in[5];
    const float* att_d = (const float*)d_in[6];
    const float* w0    = (const float*)d_in[7];
    const float* b0    = (const float*)d_in[8];
    const float* w1    = (const float*)d_in[9];
    const float* b1    = (const float*)d_in[10];
    float* y = (float*)d_out;

    decode_k<<<EB + SCAN_NBLK + 65, 256>>>(edge, ptr, emb, lin_w);
    scan_k<<<SCAN_NBLK, 256>>>();
    fill_h1_k<<<EB + WB, 256>>>(emb);

    for (int l = 1; l < 3; l++) {
        int sel = l - 1;   // 0: hA->hB, 1: hB->hA
        gemm_k<<<(N_NODES + 127) / 128, 256>>>(lin_w + l * D * D, sel);
        att_k<<<WB, 256>>>(att_s + l * NHEAD * DH, att_d + l * NHEAD * DH);
        agg_k<<<WB, 256>>>(sel);
    }

    readout_k<<<((N_NODES + 63) / 64 * 32 + 255) / 256, 256>>>();
    mlp_k<<<B_GR, 64>>>(w0, b0, w1, b1, y);
}